// round 1
// baseline (speedup 1.0000x reference)
#include <cuda_runtime.h>
#include <math.h>

// Problem constants
constexpr int NB   = 16;    // batch
constexpr int CH   = 512;   // channels
constexpr int NPIX = 1024;  // H*W
constexpr int NGRP = 32;
constexpr int CPG  = CH / NGRP;           // 16 channels per group
constexpr long long HSZ   = (long long)NB * CH * NPIX;        // 8.4M
constexpr long long QKVSZ = (long long)NB * 3 * CH * NPIX;    // 25.2M
constexpr long long ATTSZ = (long long)NB * NPIX * NPIX;      // 16.8M

// Scratch (allocation-free rule: __device__ globals)
__device__ float g_h[HSZ];
__device__ float g_qkv[QKVSZ];
__device__ float g_attn[ATTSZ];
__device__ float g_o[HSZ];

// ---------------------------------------------------------------------------
// GroupNorm: one block per (b,g). Each group = CPG*NPIX = 16384 contiguous floats.
// ---------------------------------------------------------------------------
__global__ __launch_bounds__(256) void groupnorm_kernel(
    const float* __restrict__ x, const float* __restrict__ gamma,
    const float* __restrict__ beta, float* __restrict__ h)
{
    const int GSZ = CPG * NPIX;          // 16384
    const int bg  = blockIdx.x;          // b*NGRP + g
    const float* xp = x + (long long)bg * GSZ;
    float*       hp = h + (long long)bg * GSZ;
    const int tid = threadIdx.x;

    float s = 0.f, ss = 0.f;
    const float4* xv = (const float4*)xp;
    for (int i = tid; i < GSZ / 4; i += 256) {
        float4 v = xv[i];
        s  += v.x + v.y + v.z + v.w;
        ss += v.x * v.x + v.y * v.y + v.z * v.z + v.w * v.w;
    }
    __shared__ float rs[256], rss[256];
    rs[tid] = s; rss[tid] = ss;
    __syncthreads();
    for (int o = 128; o > 0; o >>= 1) {
        if (tid < o) { rs[tid] += rs[tid + o]; rss[tid] += rss[tid + o]; }
        __syncthreads();
    }
    const float mu   = rs[0] / GSZ;
    const float var  = rss[0] / GSZ - mu * mu;
    const float rinv = rsqrtf(var + 1e-5f);

    const int g = bg % NGRP;
    const int cbase = g * CPG;
    float4* hv = (float4*)hp;
    for (int i = tid; i < GSZ / 4; i += 256) {
        float4 v = xv[i];
        const int c = cbase + (i * 4) / NPIX;   // NPIX%4==0 -> same channel for all 4
        const float ga = gamma[c] * rinv, be = beta[c] - mu * rinv * gamma[c];
        v.x = v.x * ga + be; v.y = v.y * ga + be;
        v.z = v.z * ga + be; v.w = v.w * ga + be;
        hv[i] = v;
    }
}

// ---------------------------------------------------------------------------
// Templated SGEMM. 64x64 tile, BK=16, 256 threads, 4x4 microtile.
// MODE 0 (NN): C[M,N] = A[M,K] * B[K,N]
// MODE 1 (TN): C[M,N] = A[K,M]^T * B[K,N]     (lda of A = M)
// MODE 2 (NT): C[M,N] = A[M,K] * B[N,K]^T     (ldb of B = K)
// Epilogue: * scale, + bias[m] (opt), + resid[m*N+n] (opt)
// All dims assumed divisible by 64 / 16 (true for this problem).
// ---------------------------------------------------------------------------
template<int MODE, bool BIAS, bool RES>
__global__ __launch_bounds__(256) void sgemm_kernel(
    const float* __restrict__ A, const float* __restrict__ B,
    float* __restrict__ Cc, int M, int N, int K,
    long long sA, long long sB, long long sC,
    const float* __restrict__ bias,
    const float* __restrict__ resid, long long sR, float scale)
{
    const int bz = blockIdx.z;
    A  += (long long)bz * sA;
    B  += (long long)bz * sB;
    Cc += (long long)bz * sC;
    const float* rp = RES ? (resid + (long long)bz * sR) : nullptr;

    const int m0 = blockIdx.y * 64;
    const int n0 = blockIdx.x * 64;

    __shared__ float As[16][68];   // [k][m]
    __shared__ float Bs[16][68];   // [k][n]

    const int tid = threadIdx.x;
    const int tx = tid % 16, ty = tid / 16;

    float acc[4][4] = {};

    for (int k0 = 0; k0 < K; k0 += 16) {
        // ---- load A tile into As[k][m]
        if (MODE == 0 || MODE == 2) {           // A row-major [M,K]
            const int ar = tid >> 2;            // 0..63  (m)
            const int ac = tid & 3;             // 0..3   (k quad)
            float4 v = *(const float4*)&A[(long long)(m0 + ar) * K + k0 + ac * 4];
            As[ac * 4 + 0][ar] = v.x; As[ac * 4 + 1][ar] = v.y;
            As[ac * 4 + 2][ar] = v.z; As[ac * 4 + 3][ar] = v.w;
        } else {                                 // TN: A row-major [K,M], lda=M
            const int kr = tid >> 4;            // 0..15 (k)
            const int mc = tid & 15;            // 0..15 (m quad)
            float4 v = *(const float4*)&A[(long long)(k0 + kr) * M + m0 + mc * 4];
            As[kr][mc * 4 + 0] = v.x; As[kr][mc * 4 + 1] = v.y;
            As[kr][mc * 4 + 2] = v.z; As[kr][mc * 4 + 3] = v.w;
        }
        // ---- load B tile into Bs[k][n]
        if (MODE == 0 || MODE == 1) {           // B row-major [K,N]
            const int kr = tid >> 4;
            const int nc = tid & 15;
            float4 v = *(const float4*)&B[(long long)(k0 + kr) * N + n0 + nc * 4];
            Bs[kr][nc * 4 + 0] = v.x; Bs[kr][nc * 4 + 1] = v.y;
            Bs[kr][nc * 4 + 2] = v.z; Bs[kr][nc * 4 + 3] = v.w;
        } else {                                 // NT: B row-major [N,K], ldb=K
            const int nr = tid >> 2;            // 0..63 (n)
            const int kc = tid & 3;             // 0..3  (k quad)
            float4 v = *(const float4*)&B[(long long)(n0 + nr) * K + k0 + kc * 4];
            Bs[kc * 4 + 0][nr] = v.x; Bs[kc * 4 + 1][nr] = v.y;
            Bs[kc * 4 + 2][nr] = v.z; Bs[kc * 4 + 3][nr] = v.w;
        }
        __syncthreads();

        #pragma unroll
        for (int kk = 0; kk < 16; kk++) {
            float a[4], bv[4];
            #pragma unroll
            for (int i = 0; i < 4; i++) a[i]  = As[kk][ty * 4 + i];
            #pragma unroll
            for (int j = 0; j < 4; j++) bv[j] = Bs[kk][tx * 4 + j];
            #pragma unroll
            for (int i = 0; i < 4; i++)
                #pragma unroll
                for (int j = 0; j < 4; j++)
                    acc[i][j] = fmaf(a[i], bv[j], acc[i][j]);
        }
        __syncthreads();
    }

    #pragma unroll
    for (int i = 0; i < 4; i++) {
        const int m = m0 + ty * 4 + i;
        const float bval = BIAS ? bias[m] : 0.f;
        #pragma unroll
        for (int j = 0; j < 4; j++) {
            const int n = n0 + tx * 4 + j;
            float v = acc[i][j] * scale + bval;
            if (RES) v += rp[(long long)m * N + n];
            Cc[(long long)m * N + n] = v;
        }
    }
}

// ---------------------------------------------------------------------------
// Row softmax over 1024 elements, one block per row, 256 threads x 4 elems.
// ---------------------------------------------------------------------------
__global__ __launch_bounds__(256) void softmax_kernel(float* __restrict__ attn)
{
    const long long row = blockIdx.x;
    float4* p = (float4*)(attn + row * NPIX);
    const int tid = threadIdx.x;

    float4 v = p[tid];
    float m = fmaxf(fmaxf(v.x, v.y), fmaxf(v.z, v.w));

    __shared__ float red[256];
    red[tid] = m; __syncthreads();
    for (int o = 128; o > 0; o >>= 1) {
        if (tid < o) red[tid] = fmaxf(red[tid], red[tid + o]);
        __syncthreads();
    }
    const float rmax = red[0];
    __syncthreads();

    v.x = expf(v.x - rmax); v.y = expf(v.y - rmax);
    v.z = expf(v.z - rmax); v.w = expf(v.w - rmax);
    float s = v.x + v.y + v.z + v.w;
    red[tid] = s; __syncthreads();
    for (int o = 128; o > 0; o >>= 1) {
        if (tid < o) red[tid] += red[tid + o];
        __syncthreads();
    }
    const float rinv = 1.f / red[0];
    v.x *= rinv; v.y *= rinv; v.z *= rinv; v.w *= rinv;
    p[tid] = v;
}

// ---------------------------------------------------------------------------
extern "C" void kernel_launch(void* const* d_in, const int* in_sizes, int n_in,
                              void* d_out, int out_size)
{
    const float* x      = (const float*)d_in[0];  // [16,512,32,32]
    const float* gamma  = (const float*)d_in[1];  // [512]
    const float* beta   = (const float*)d_in[2];  // [512]
    const float* w_qkv  = (const float*)d_in[3];  // [1536,512]
    const float* b_qkv  = (const float*)d_in[4];  // [1536]
    const float* w_proj = (const float*)d_in[5];  // [512,512]
    const float* b_proj = (const float*)d_in[6];  // [512]
    float* out = (float*)d_out;

    float *h, *qkv, *attn, *o;
    cudaGetSymbolAddress((void**)&h,    g_h);
    cudaGetSymbolAddress((void**)&qkv,  g_qkv);
    cudaGetSymbolAddress((void**)&attn, g_attn);
    cudaGetSymbolAddress((void**)&o,    g_o);

    const long long sH   = (long long)CH * NPIX;       // 512*1024
    const long long sQKV = (long long)3 * CH * NPIX;   // 1536*1024
    const long long sATT = (long long)NPIX * NPIX;     // 1024*1024

    // 1. GroupNorm
    groupnorm_kernel<<<NB * NGRP, 256>>>(x, gamma, beta, h);

    // 2. QKV: per batch [1536,512] @ [512,1024] + bias
    sgemm_kernel<0, true, false><<<dim3(NPIX / 64, 1536 / 64, NB), 256>>>(
        w_qkv, h, qkv, 1536, NPIX, CH,
        0, sH, sQKV, b_qkv, nullptr, 0, 1.f);

    // 3. Scores: S = Q^T K / sqrt(C)   (Q,K are [C,N] per batch)
    const float scale = rsqrtf((float)CH);
    sgemm_kernel<1, false, false><<<dim3(NPIX / 64, NPIX / 64, NB), 256>>>(
        qkv /*Q*/, qkv + (long long)CH * NPIX /*K*/, attn,
        NPIX, NPIX, CH,
        sQKV, sQKV, sATT, nullptr, nullptr, 0, scale);

    // 4. Softmax rows
    softmax_kernel<<<NB * NPIX, 256>>>(attn);

    // 5. O = V @ P^T   (V [C,N], P [N,N])
    sgemm_kernel<2, false, false><<<dim3(NPIX / 64, CH / 64, NB), 256>>>(
        qkv + (long long)2 * CH * NPIX /*V*/, attn, o,
        CH, NPIX, NPIX,
        sQKV, sATT, sH, nullptr, nullptr, 0, 1.f);

    // 6. Proj + bias + residual
    sgemm_kernel<0, true, true><<<dim3(NPIX / 64, CH / 64, NB), 256>>>(
        w_proj, o, out, CH, NPIX, CH,
        0, sH, sH, b_proj, x, sH, 1.f);
}

// round 3
// speedup vs baseline: 3.6567x; 3.6567x over previous
#include <cuda_runtime.h>
#include <cuda_bf16.h>
#include <math.h>
#include <stdint.h>

// ---------------------------------------------------------------------------
// Problem constants
// ---------------------------------------------------------------------------
constexpr int NB   = 16;
constexpr int CH   = 512;
constexpr int NPIX = 1024;
constexpr int NGRP = 32;

// GEMM tiling
constexpr int TM = 128, TN = 128, TK = 32;

// smem: two operand stages (A 16KB + B 16KB each) + fp32 epilogue stage
constexpr int STAGE_BYTES = 32768;                  // per double-buffer stage
constexpr int OFF_STAGE   = 2 * STAGE_BYTES;        // 65536
constexpr int SPITCH      = 129;                    // fp32 stage pitch
constexpr int SMEM_BYTES  = OFF_STAGE + TM * SPITCH * 4;  // 131584

// ---------------------------------------------------------------------------
// Scratch (__device__ globals; allocation-free rule). hi/lo split-bf16 pairs.
// ---------------------------------------------------------------------------
#define BALIGN __align__(256)
__device__ BALIGN __nv_bfloat16 g_ht_h[(size_t)NB * NPIX * CH];
__device__ BALIGN __nv_bfloat16 g_ht_l[(size_t)NB * NPIX * CH];
__device__ BALIGN __nv_bfloat16 g_q_h [(size_t)NB * NPIX * CH];
__device__ BALIGN __nv_bfloat16 g_q_l [(size_t)NB * NPIX * CH];
__device__ BALIGN __nv_bfloat16 g_k_h [(size_t)NB * NPIX * CH];
__device__ BALIGN __nv_bfloat16 g_k_l [(size_t)NB * NPIX * CH];
__device__ BALIGN __nv_bfloat16 g_v_h [(size_t)NB * CH * NPIX];
__device__ BALIGN __nv_bfloat16 g_v_l [(size_t)NB * CH * NPIX];
__device__ BALIGN __nv_bfloat16 g_p_h [(size_t)NB * NPIX * NPIX];
__device__ BALIGN __nv_bfloat16 g_p_l [(size_t)NB * NPIX * NPIX];
__device__ BALIGN __nv_bfloat16 g_ot_h[(size_t)NB * NPIX * CH];
__device__ BALIGN __nv_bfloat16 g_ot_l[(size_t)NB * NPIX * CH];
__device__ BALIGN __nv_bfloat16 g_wq_h[(size_t)3 * CH * CH];
__device__ BALIGN __nv_bfloat16 g_wq_l[(size_t)3 * CH * CH];
__device__ BALIGN __nv_bfloat16 g_wp_h[(size_t)CH * CH];
__device__ BALIGN __nv_bfloat16 g_wp_l[(size_t)CH * CH];
__device__ BALIGN float         g_attn[(size_t)NB * NPIX * NPIX];
__device__ float g_stats[NB * NGRP * 2];

// ---------------------------------------------------------------------------
// helpers
// ---------------------------------------------------------------------------
__device__ __forceinline__ uint32_t smem_u32(const void* p) {
    uint32_t a;
    asm("{ .reg .u64 t; cvta.to.shared.u64 t, %1; cvt.u32.u64 %0, t; }" : "=r"(a) : "l"(p));
    return a;
}
__device__ __forceinline__ void split_bf16(float v, __nv_bfloat16& h, __nv_bfloat16& l) {
    h = __float2bfloat16(v);
    l = __float2bfloat16(v - __bfloat162float(h));
}

#define CP16(sm, gp) asm volatile("cp.async.cg.shared.global [%0], [%1], 16;" :: "r"(sm), "l"(gp))
#define CP_COMMIT()  asm volatile("cp.async.commit_group;" ::: "memory")
#define CP_WAIT0()   asm volatile("cp.async.wait_group 0;" ::: "memory")
#define CP_WAIT1()   asm volatile("cp.async.wait_group 1;" ::: "memory")

#define LDSM4(r0, r1, r2, r3, a) \
    asm volatile("ldmatrix.sync.aligned.m8n8.x4.shared.b16 {%0,%1,%2,%3}, [%4];" \
                 : "=r"(r0), "=r"(r1), "=r"(r2), "=r"(r3) : "r"(a))

#define MMA_BF16(d, a, b0, b1) \
    asm volatile("mma.sync.aligned.m16n8k16.row.col.f32.bf16.bf16.f32 " \
                 "{%0,%1,%2,%3},{%4,%5,%6,%7},{%8,%9},{%0,%1,%2,%3};" \
                 : "+f"((d)[0]), "+f"((d)[1]), "+f"((d)[2]), "+f"((d)[3]) \
                 : "r"((a)[0]), "r"((a)[1]), "r"((a)[2]), "r"((a)[3]), "r"(b0), "r"(b1))

// ---------------------------------------------------------------------------
// GroupNorm phase 1: per-(b,g) mean / rstd
// ---------------------------------------------------------------------------
__global__ __launch_bounds__(256) void gn_stats_kernel(
    const float* __restrict__ x, float* __restrict__ stats)
{
    const int GSZ = (CH / NGRP) * NPIX;
    const int bg  = blockIdx.x;
    const float4* xv = (const float4*)(x + (size_t)bg * GSZ);
    const int tid = threadIdx.x;

    float s = 0.f, ss = 0.f;
    for (int i = tid; i < GSZ / 4; i += 256) {
        float4 v = xv[i];
        s  += v.x + v.y + v.z + v.w;
        ss += v.x * v.x + v.y * v.y + v.z * v.z + v.w * v.w;
    }
    __shared__ float rs[256], rss[256];
    rs[tid] = s; rss[tid] = ss;
    __syncthreads();
    for (int o = 128; o > 0; o >>= 1) {
        if (tid < o) { rs[tid] += rs[tid + o]; rss[tid] += rss[tid + o]; }
        __syncthreads();
    }
    if (tid == 0) {
        float mu  = rs[0] / GSZ;
        float var = rss[0] / GSZ - mu * mu;
        stats[bg * 2]     = mu;
        stats[bg * 2 + 1] = rsqrtf(var + 1e-5f);
    }
}

// ---------------------------------------------------------------------------
// GroupNorm phase 2: normalize + split + transpose -> ht[b][p][c]
// ---------------------------------------------------------------------------
__global__ __launch_bounds__(256) void gn_apply_kernel(
    const float* __restrict__ x, const float* __restrict__ gamma,
    const float* __restrict__ beta, const float* __restrict__ stats,
    __nv_bfloat16* __restrict__ hth, __nv_bfloat16* __restrict__ htl)
{
    __shared__ float s[32][33];
    const int p0 = blockIdx.x * 32, c0 = blockIdx.y * 32, b = blockIdx.z;
    const int tid = threadIdx.x;

    #pragma unroll
    for (int q = 0; q < 4; q++) {
        int ci = (tid >> 5) + q * 8, pj = tid & 31;
        int c = c0 + ci;
        float xv = x[((size_t)b * CH + c) * NPIX + p0 + pj];
        int g = c >> 4;
        float mu = stats[(b * NGRP + g) * 2], rinv = stats[(b * NGRP + g) * 2 + 1];
        s[ci][pj] = (xv - mu) * rinv * gamma[c] + beta[c];
    }
    __syncthreads();
    #pragma unroll
    for (int q = 0; q < 4; q++) {
        int cj = tid & 31, pi = (tid >> 5) + q * 8;
        __nv_bfloat16 h, l;
        split_bf16(s[cj][pi], h, l);
        size_t o = (size_t)b * NPIX * CH + (size_t)(p0 + pi) * CH + c0 + cj;
        hth[o] = h; htl[o] = l;
    }
}

// ---------------------------------------------------------------------------
// Row softmax -> split-bf16 P
// ---------------------------------------------------------------------------
__global__ __launch_bounds__(256) void softmax_kernel(
    const float* __restrict__ attn,
    __nv_bfloat16* __restrict__ ph, __nv_bfloat16* __restrict__ pl)
{
    const size_t row = blockIdx.x;
    const float4* p = (const float4*)(attn + row * NPIX);
    const int tid = threadIdx.x;

    float4 v = p[tid];
    float m = fmaxf(fmaxf(v.x, v.y), fmaxf(v.z, v.w));

    __shared__ float red[256];
    red[tid] = m; __syncthreads();
    for (int o = 128; o > 0; o >>= 1) {
        if (tid < o) red[tid] = fmaxf(red[tid], red[tid + o]);
        __syncthreads();
    }
    const float rmax = red[0];
    __syncthreads();

    v.x = expf(v.x - rmax); v.y = expf(v.y - rmax);
    v.z = expf(v.z - rmax); v.w = expf(v.w - rmax);
    red[tid] = v.x + v.y + v.z + v.w; __syncthreads();
    for (int o = 128; o > 0; o >>= 1) {
        if (tid < o) red[tid] += red[tid + o];
        __syncthreads();
    }
    const float rinv = 1.f / red[0];
    float vals[4] = {v.x * rinv, v.y * rinv, v.z * rinv, v.w * rinv};
    __nv_bfloat16 hh[4], ll[4];
    #pragma unroll
    for (int i = 0; i < 4; i++) split_bf16(vals[i], hh[i], ll[i]);
    size_t o = row * NPIX + tid * 4;
    *(__nv_bfloat162*)(ph + o)     = __nv_bfloat162(hh[0], hh[1]);
    *(__nv_bfloat162*)(ph + o + 2) = __nv_bfloat162(hh[2], hh[3]);
    *(__nv_bfloat162*)(pl + o)     = __nv_bfloat162(ll[0], ll[1]);
    *(__nv_bfloat162*)(pl + o + 2) = __nv_bfloat162(ll[2], ll[3]);
}

// ---------------------------------------------------------------------------
// fp32 -> split-bf16 (weights)
// ---------------------------------------------------------------------------
__global__ __launch_bounds__(256) void pack_kernel(
    const float* __restrict__ w,
    __nv_bfloat16* __restrict__ oh, __nv_bfloat16* __restrict__ ol, int n)
{
    int i = (blockIdx.x * 256 + threadIdx.x) * 2;
    if (i < n) {
        __nv_bfloat16 h0, l0, h1, l1;
        split_bf16(w[i], h0, l0);
        split_bf16(w[i + 1], h1, l1);
        *(__nv_bfloat162*)(oh + i) = __nv_bfloat162(h0, h1);
        *(__nv_bfloat162*)(ol + i) = __nv_bfloat162(l0, l1);
    }
}

// ---------------------------------------------------------------------------
// Split-bf16 HMMA GEMM: D[m][n] = sum_k A[m][k]*B[n][k]  (both k-major)
// CTA 128x128, BK=32, 8 warps (2M x 4N), warp tile 64x32.
// smem row = 128B: [hi 32 bf16 | lo 32 bf16], 16B units XOR-swizzled by row&7.
// EPI 0: QKV  1: scores  2: PV  3: proj(+bias+residual)
// ---------------------------------------------------------------------------
template<int EPI>
__global__ __launch_bounds__(256) void tc_gemm(
    const __nv_bfloat16* __restrict__ Agh, const __nv_bfloat16* __restrict__ Agl,
    const __nv_bfloat16* __restrict__ Bgh, const __nv_bfloat16* __restrict__ Bgl,
    long long sAb, long long sBb, int ldA, int ldB, int K,
    const float* __restrict__ bias, float scale,
    float* __restrict__ outf,
    __nv_bfloat16* __restrict__ o0h, __nv_bfloat16* __restrict__ o0l,
    __nv_bfloat16* __restrict__ o1h, __nv_bfloat16* __restrict__ o1l,
    __nv_bfloat16* __restrict__ o2h, __nv_bfloat16* __restrict__ o2l,
    const float* __restrict__ resid)
{
    extern __shared__ char smem[];
    const uint32_t sb = smem_u32(smem);
    const int tid = threadIdx.x;
    const int lane = tid & 31, wid = tid >> 5;
    const int bz = blockIdx.z;
    const int m0 = blockIdx.y * TM;
    const int n0 = blockIdx.x * TN;

    const __nv_bfloat16* Ah = Agh + (size_t)bz * sAb + (size_t)m0 * ldA;
    const __nv_bfloat16* Al = Agl + (size_t)bz * sAb + (size_t)m0 * ldA;
    const __nv_bfloat16* Bh = Bgh + (size_t)bz * sBb + (size_t)n0 * ldB;
    const __nv_bfloat16* Bl = Bgl + (size_t)bz * sBb + (size_t)n0 * ldB;

    // loader mapping: row = tid>>1 (0..127), units (tid&1)*2 + {0,1}
    const int lrow = tid >> 1;
    const int lu0  = (tid & 1) * 2;
    const int lswz = lrow & 7;

    auto load_tile = [&](int buf, int k0) {
        const uint32_t sa = sb + buf * STAGE_BYTES;
        const uint32_t sbB = sa + 16384;
        #pragma unroll
        for (int j = 0; j < 2; j++) {
            const int u = lu0 + j;
            const int gk = k0 + u * 8;
            CP16(sa  + lrow * 128 + ((u       ^ lswz) << 4), Ah + (size_t)lrow * ldA + gk);
            CP16(sa  + lrow * 128 + (((u + 4) ^ lswz) << 4), Al + (size_t)lrow * ldA + gk);
            CP16(sbB + lrow * 128 + ((u       ^ lswz) << 4), Bh + (size_t)lrow * ldB + gk);
            CP16(sbB + lrow * 128 + (((u + 4) ^ lswz) << 4), Bl + (size_t)lrow * ldB + gk);
        }
    };

    // warp layout
    const int wm = wid >> 2, wn = wid & 3;
    const int m_base = wm * 64, n_base = wn * 32;

    // ldmatrix lane mapping
    const int amat = lane >> 3;
    const int arow = (amat & 1) * 8 + (lane & 7);   // + m_base + mt*16
    const int auadd = amat >> 1;
    const int bmat = lane >> 3;
    const int bnrow = (bmat >> 1) * 8 + (lane & 7); // + n_base + np*16
    const int buadd = bmat & 1;

    float acc[4][4][4] = {};

    load_tile(0, 0);
    CP_COMMIT();

    int buf = 0;
    for (int k0 = 0; k0 < K; k0 += TK) {
        __syncthreads();               // all warps done with buf^1 compute
        if (k0 + TK < K) {
            load_tile(buf ^ 1, k0 + TK);
            CP_COMMIT();
            CP_WAIT1();
        } else {
            CP_WAIT0();
        }
        __syncthreads();               // current tile visible to all

        const uint32_t sa  = sb + buf * STAGE_BYTES;
        const uint32_t sbB = sa + 16384;

        #pragma unroll
        for (int kk = 0; kk < 2; kk++) {
            uint32_t ah[4][4], al[4][4], bh[8], bl[8];
            #pragma unroll
            for (int mt = 0; mt < 4; mt++) {
                const int row = m_base + mt * 16 + arow;
                const int rx = row & 7;
                const uint32_t base = sa + row * 128;
                const int uh = kk * 2 + auadd;
                LDSM4(ah[mt][0], ah[mt][1], ah[mt][2], ah[mt][3], base + ((uh ^ rx) << 4));
                LDSM4(al[mt][0], al[mt][1], al[mt][2], al[mt][3], base + (((uh + 4) ^ rx) << 4));
            }
            #pragma unroll
            for (int np = 0; np < 2; np++) {
                const int n = n_base + np * 16 + bnrow;
                const int rx = n & 7;
                const uint32_t base = sbB + n * 128;
                const int uh = kk * 2 + buadd;
                LDSM4(bh[np * 4 + 0], bh[np * 4 + 1], bh[np * 4 + 2], bh[np * 4 + 3],
                      base + ((uh ^ rx) << 4));
                LDSM4(bl[np * 4 + 0], bl[np * 4 + 1], bl[np * 4 + 2], bl[np * 4 + 3],
                      base + (((uh + 4) ^ rx) << 4));
            }
            #pragma unroll
            for (int mt = 0; mt < 4; mt++) {
                #pragma unroll
                for (int nt = 0; nt < 4; nt++) {
                    const int r = (nt >> 1) * 4 + (nt & 1) * 2;
                    MMA_BF16(acc[mt][nt], ah[mt], bh[r], bh[r + 1]);
                    MMA_BF16(acc[mt][nt], ah[mt], bl[r], bl[r + 1]);
                    MMA_BF16(acc[mt][nt], al[mt], bh[r], bh[r + 1]);
                }
            }
        }
        buf ^= 1;
    }

    // ---- stage accumulators to smem fp32 ----
    __syncthreads();
    float* s = (float*)(smem + OFF_STAGE);
    #pragma unroll
    for (int mt = 0; mt < 4; mt++)
        #pragma unroll
        for (int nt = 0; nt < 4; nt++)
            #pragma unroll
            for (int r = 0; r < 4; r++) {
                const int row = m_base + mt * 16 + (lane >> 2) + (r >= 2 ? 8 : 0);
                const int col = n_base + nt * 8 + (lane & 3) * 2 + (r & 1);
                s[row * SPITCH + col] = acc[mt][nt][r];
            }
    __syncthreads();

    // ---- writers ----
    if (EPI == 0 && m0 < 2 * CH) {
        // Q or K tile: [p][c] output, m-fast pairs for coalescing over c
        __nv_bfloat16* dh = (m0 < CH ? o0h : o1h) + (size_t)bz * NPIX * CH;
        __nv_bfloat16* dl = (m0 < CH ? o0l : o1l) + (size_t)bz * NPIX * CH;
        const int coff = m0 & (CH - 1);
        for (int it = 0; it < 32; it++) {
            const int idx = it * 512 + tid * 2;
            const int n = idx >> 7, m = idx & 127;
            float v0 = s[m * SPITCH + n] + bias[m0 + m];
            float v1 = s[(m + 1) * SPITCH + n] + bias[m0 + m + 1];
            __nv_bfloat16 h0, l0, h1, l1;
            split_bf16(v0, h0, l0); split_bf16(v1, h1, l1);
            const size_t o = (size_t)(n0 + n) * CH + coff + m;
            *(__nv_bfloat162*)(dh + o) = __nv_bfloat162(h0, h1);
            *(__nv_bfloat162*)(dl + o) = __nv_bfloat162(l0, l1);
        }
    } else {
        for (int it = 0; it < 32; it++) {
            const int idx = it * 512 + tid * 2;
            const int m = idx >> 7, n = idx & 127;
            float v0 = s[m * SPITCH + n];
            float v1 = s[m * SPITCH + n + 1];
            if (EPI == 0) {          // V tile -> v[b][c][p]
                const int c = m0 - 2 * CH + m;
                v0 += bias[m0 + m]; v1 += bias[m0 + m];
                __nv_bfloat16 h0, l0, h1, l1;
                split_bf16(v0, h0, l0); split_bf16(v1, h1, l1);
                const size_t o = ((size_t)bz * CH + c) * NPIX + n0 + n;
                *(__nv_bfloat162*)(o2h + o) = __nv_bfloat162(h0, h1);
                *(__nv_bfloat162*)(o2l + o) = __nv_bfloat162(l0, l1);
            } else if (EPI == 1) {   // scores fp32
                const size_t o = ((size_t)bz * NPIX + m0 + m) * NPIX + n0 + n;
                *(float2*)(outf + o) = make_float2(v0 * scale, v1 * scale);
            } else if (EPI == 2) {   // Ot split [p][c]
                __nv_bfloat16 h0, l0, h1, l1;
                split_bf16(v0, h0, l0); split_bf16(v1, h1, l1);
                const size_t o = ((size_t)bz * NPIX + m0 + m) * CH + n0 + n;
                *(__nv_bfloat162*)(o0h + o) = __nv_bfloat162(h0, h1);
                *(__nv_bfloat162*)(o0l + o) = __nv_bfloat162(l0, l1);
            } else {                 // proj + bias + residual
                const float bv = bias[m0 + m];
                const size_t o = ((size_t)bz * CH + m0 + m) * NPIX + n0 + n;
                float2 rv = *(const float2*)(resid + o);
                *(float2*)(outf + o) = make_float2(v0 + bv + rv.x, v1 + bv + rv.y);
            }
        }
    }
}

// ---------------------------------------------------------------------------
extern "C" void kernel_launch(void* const* d_in, const int* in_sizes, int n_in,
                              void* d_out, int out_size)
{
    const float* x      = (const float*)d_in[0];
    const float* gamma  = (const float*)d_in[1];
    const float* beta   = (const float*)d_in[2];
    const float* w_qkv  = (const float*)d_in[3];
    const float* b_qkv  = (const float*)d_in[4];
    const float* w_proj = (const float*)d_in[5];
    const float* b_proj = (const float*)d_in[6];
    float* out = (float*)d_out;

    __nv_bfloat16 *hth, *htl, *qh, *ql, *kh, *kl, *vh, *vl, *ph, *pl,
                  *oth, *otl, *wqh, *wql, *wph, *wpl;
    float *attn, *stats;
    cudaGetSymbolAddress((void**)&hth, g_ht_h); cudaGetSymbolAddress((void**)&htl, g_ht_l);
    cudaGetSymbolAddress((void**)&qh,  g_q_h ); cudaGetSymbolAddress((void**)&ql,  g_q_l );
    cudaGetSymbolAddress((void**)&kh,  g_k_h ); cudaGetSymbolAddress((void**)&kl,  g_k_l );
    cudaGetSymbolAddress((void**)&vh,  g_v_h ); cudaGetSymbolAddress((void**)&vl,  g_v_l );
    cudaGetSymbolAddress((void**)&ph,  g_p_h ); cudaGetSymbolAddress((void**)&pl,  g_p_l );
    cudaGetSymbolAddress((void**)&oth, g_ot_h); cudaGetSymbolAddress((void**)&otl, g_ot_l);
    cudaGetSymbolAddress((void**)&wqh, g_wq_h); cudaGetSymbolAddress((void**)&wql, g_wq_l);
    cudaGetSymbolAddress((void**)&wph, g_wp_h); cudaGetSymbolAddress((void**)&wpl, g_wp_l);
    cudaGetSymbolAddress((void**)&attn, g_attn);
    cudaGetSymbolAddress((void**)&stats, g_stats);

    cudaFuncSetAttribute(tc_gemm<0>, cudaFuncAttributeMaxDynamicSharedMemorySize, SMEM_BYTES);
    cudaFuncSetAttribute(tc_gemm<1>, cudaFuncAttributeMaxDynamicSharedMemorySize, SMEM_BYTES);
    cudaFuncSetAttribute(tc_gemm<2>, cudaFuncAttributeMaxDynamicSharedMemorySize, SMEM_BYTES);
    cudaFuncSetAttribute(tc_gemm<3>, cudaFuncAttributeMaxDynamicSharedMemorySize, SMEM_BYTES);

    const long long sH = (long long)NPIX * CH;
    const long long sP = (long long)NPIX * NPIX;

    pack_kernel<<<(3 * CH * CH / 2 + 255) / 256, 256>>>(w_qkv, wqh, wql, 3 * CH * CH);
    pack_kernel<<<(CH * CH / 2 + 255) / 256, 256>>>(w_proj, wph, wpl, CH * CH);
    gn_stats_kernel<<<NB * NGRP, 256>>>(x, stats);
    gn_apply_kernel<<<dim3(NPIX / 32, CH / 32, NB), 256>>>(x, gamma, beta, stats, hth, htl);

    // QKV: A = w_qkv [1536,512], B = ht[b][p][c] -> q/k [p][c], v [c][p]
    tc_gemm<0><<<dim3(NPIX / TN, 1536 / TM, NB), 256, SMEM_BYTES>>>(
        wqh, wql, hth, htl, 0, sH, CH, CH, CH,
        b_qkv, 1.f, nullptr, qh, ql, kh, kl, vh, vl, nullptr);

    // scores: q[i][c] . k[j][c] * scale -> attn fp32
    tc_gemm<1><<<dim3(NPIX / TN, NPIX / TM, NB), 256, SMEM_BYTES>>>(
        qh, ql, kh, kl, sH, sH, CH, CH, CH,
        nullptr, 1.0f / sqrtf((float)CH), attn,
        nullptr, nullptr, nullptr, nullptr, nullptr, nullptr, nullptr);

    softmax_kernel<<<NB * NPIX, 256>>>(attn, ph, pl);

    // PV: p[i][j] . v[c][j] -> ot[p][c]
    tc_gemm<2><<<dim3(CH / TN, NPIX / TM, NB), 256, SMEM_BYTES>>>(
        ph, pl, vh, vl, sP, sH, NPIX, NPIX, NPIX,
        nullptr, 1.f, nullptr, oth, otl,
        nullptr, nullptr, nullptr, nullptr, nullptr);

    // proj: w_proj[o][c] . ot[p][c] + bias + residual -> out [b][c][p]
    tc_gemm<3><<<dim3(NPIX / TN, CH / TM, NB), 256, SMEM_BYTES>>>(
        wph, wpl, oth, otl, 0, sH, CH, CH, CH,
        b_proj, 1.f, out, nullptr, nullptr, nullptr, nullptr, nullptr, nullptr, x);
}